// round 10
// baseline (speedup 1.0000x reference)
#include <cuda_runtime.h>
#include <cuda_fp16.h>
#include <cstdint>

// ---------------- configuration ----------------
#define TOK_TILE     64
#define NUM_TILES    256          // 16384 / 64  -> 2 CTAs resident per SM
#define THREADS      256          // 8 warps: 2 m-groups x 4 n-groups (Mw=32, Nw=16)
#define KB_STEPS     8            // K=256 in blocks of 32
#define NCHUNKS      64
#define NSLICES      (KB_STEPS * NCHUNKS)   // 512
#define SLICE_WORDS  1024         // 64 o x 32 k halves = 1024 b32 words
#define PF           3            // prefetch distance (chunks); ring of 4 buffers

// smem: only the x2 tile
#define X2_STRIDE    68
#define SMEM_BYTES   (TOK_TILE * X2_STRIDE * 4)   // 17408

// W pre-converted to fp16, fragment-ordered per (kb, c) slice
__device__ uint32_t g_Wh[4096 * 128];   // 2 MB

static __device__ __forceinline__ uint32_t pack_h2(float lo, float hi) {
    uint32_t r;
    asm("cvt.rn.f16x2.f32 %0, %1, %2;" : "=r"(r) : "f"(hi), "f"(lo));
    return r;
}
static __device__ __forceinline__ void mma_init(float& d0, float& d1, float& d2, float& d3,
                                                const uint32_t* a, uint32_t b0, uint32_t b1,
                                                float c0, float c1, float c2, float c3) {
    asm("mma.sync.aligned.m16n8k16.row.col.f32.f16.f16.f32 "
        "{%0,%1,%2,%3}, {%4,%5,%6,%7}, {%8,%9}, {%10,%11,%12,%13};"
        : "=f"(d0), "=f"(d1), "=f"(d2), "=f"(d3)
        : "r"(a[0]), "r"(a[1]), "r"(a[2]), "r"(a[3]), "r"(b0), "r"(b1),
          "f"(c0), "f"(c1), "f"(c2), "f"(c3));
}
static __device__ __forceinline__ void mma_acc(float& d0, float& d1, float& d2, float& d3,
                                               const uint32_t* a, uint32_t b0, uint32_t b1) {
    asm("mma.sync.aligned.m16n8k16.row.col.f32.f16.f16.f32 "
        "{%0,%1,%2,%3}, {%4,%5,%6,%7}, {%8,%9}, {%0,%1,%2,%3};"
        : "+f"(d0), "+f"(d1), "+f"(d2), "+f"(d3)
        : "r"(a[0]), "r"(a[1]), "r"(a[2]), "r"(a[3]), "r"(b0), "r"(b1));
}

// -------- W pre-transform: fp32 -> f16x2, fragment order (unchanged from R9) --------
__global__ void prep_kernel(const float* __restrict__ W) {
    int idx = blockIdx.x * 256 + threadIdx.x;      // 524,288 threads
    int s   = idx >> 10;
    int rem = idx & 1023;
    int o   = rem >> 4;
    int r   = (rem >> 2) & 3;
    int q   = rem & 3;
    int ks  = q >> 1, hb = q & 1;
    int kb  = s >> 6, c = s & 63;
    const float* src = W + (size_t)(c * 64 + o) * 256 + kb * 32 + ks * 16 + hb * 8 + r * 2;
    g_Wh[idx] = pack_h2(src[0], src[1]);
}

// this warp's B fragments for slice s: 1 LDG.128 per nt, fully coalesced
static __device__ __forceinline__ void load_frags(uint32_t bf[2][4], int s,
                                                  int cn, int gID, int tig) {
    const uint4* base = reinterpret_cast<const uint4*>(g_Wh) + (size_t)s * (SLICE_WORDS / 4);
#pragma unroll
    for (int nt = 0; nt < 2; nt++) {
        int o = cn + nt * 8 + gID;
        uint4 v = __ldg(base + o * 4 + tig);
        bf[nt][0] = v.x; bf[nt][1] = v.y; bf[nt][2] = v.z; bf[nt][3] = v.w;
    }
}

// A fragments (x1 -> fp16) for one k-block; reused across all 64 chunks
static __device__ __forceinline__ void load_A(uint32_t A[2][2][4],
                                              const float* __restrict__ x1,
                                              int tok0, int kb, int rm, int gID, int tig) {
    const float* base = x1 + (size_t)tok0 * 256 + kb * 32;
#pragma unroll
    for (int mt = 0; mt < 2; mt++) {
        const float* r0 = base + (size_t)(rm + mt * 16 + gID) * 256;
        const float* r1 = r0 + 8 * 256;
#pragma unroll
        for (int ks = 0; ks < 2; ks++) {
            int k0 = ks * 16 + tig * 2;
            float2 a0 = *reinterpret_cast<const float2*>(r0 + k0);
            float2 a1 = *reinterpret_cast<const float2*>(r1 + k0);
            float2 a2 = *reinterpret_cast<const float2*>(r0 + k0 + 8);
            float2 a3 = *reinterpret_cast<const float2*>(r1 + k0 + 8);
            A[mt][ks][0] = pack_h2(a0.x, a0.y);
            A[mt][ks][1] = pack_h2(a1.x, a1.y);
            A[mt][ks][2] = pack_h2(a2.x, a2.y);
            A[mt][ks][3] = pack_h2(a3.x, a3.y);
        }
    }
}

// one chunk: 8 HMMA (2nt x 2mt x 2ks-chain) + y epilogue
template <bool FIRST>
static __device__ __forceinline__ void chunk_mma(
    const uint32_t bf[2][4], const float* __restrict__ x2s,
    const float* __restrict__ bvec, const uint32_t A[2][2][4],
    float y[2][2][4], int c, int rm, int cn, int gID, int tig)
{
    // hoist xv loads to the top so LDS latency overlaps the mma burst
    float xv[2][2];
#pragma unroll
    for (int mt = 0; mt < 2; mt++) {
        xv[mt][0] = x2s[(rm + mt * 16 + gID) * X2_STRIDE + c];
        xv[mt][1] = x2s[(rm + mt * 16 + gID + 8) * X2_STRIDE + c];
    }
#pragma unroll
    for (int nt = 0; nt < 2; nt++) {
        float cq0 = 0.0f, cq1 = 0.0f;
        if (FIRST) {
            float2 bb = __ldg(reinterpret_cast<const float2*>(
                bvec + c * 64 + cn + nt * 8 + tig * 2));
            cq0 = bb.x; cq1 = bb.y;
        }
#pragma unroll
        for (int mt = 0; mt < 2; mt++) {
            float d0, d1, d2, d3;
            mma_init(d0, d1, d2, d3, A[mt][0], bf[nt][0], bf[nt][1], cq0, cq1, cq0, cq1);
            mma_acc (d0, d1, d2, d3, A[mt][1], bf[nt][2], bf[nt][3]);
            y[mt][nt][0] = fmaf(xv[mt][0], d0, y[mt][nt][0]);
            y[mt][nt][1] = fmaf(xv[mt][0], d1, y[mt][nt][1]);
            y[mt][nt][2] = fmaf(xv[mt][1], d2, y[mt][nt][2]);
            y[mt][nt][3] = fmaf(xv[mt][1], d3, y[mt][nt][3]);
        }
    }
}

__global__ void __launch_bounds__(THREADS, 2)
metaLinear_kernel(const float* __restrict__ x1, const float* __restrict__ x2,
                  const float* __restrict__ bvec, float* __restrict__ out)
{
    extern __shared__ float x2s[];

    const int tid  = threadIdx.x;
    const int lane = tid & 31, wid = tid >> 5;
    const int wm = wid >> 2, wn = wid & 3;          // 2 m-groups x 4 n-groups
    const int gID = lane >> 2, tig = lane & 3;
    const int tok0 = blockIdx.x * TOK_TILE;
    const int rm = wm * 32;
    const int cn = wn * 16;

    // stage x2 tile (padded stride); the ONLY block barrier
    for (int i = tid; i < TOK_TILE * 64; i += THREADS) {
        int r = i >> 6, c = i & 63;
        x2s[r * X2_STRIDE + c] = x2[(size_t)(tok0 + r) * 64 + c];
    }

    uint32_t A[2][2][4];
    float y[2][2][4];
#pragma unroll
    for (int mt = 0; mt < 2; mt++)
#pragma unroll
        for (int nt = 0; nt < 2; nt++)
#pragma unroll
            for (int j = 0; j < 4; j++) y[mt][nt][j] = 0.0f;

    load_A(A, x1, tok0, 0, rm, gID, tig);

    // B-fragment ring: 4 buffers, prefetch distance PF=3
    uint32_t bf[4][2][4];
    load_frags(bf[0], 0, cn, gID, tig);
    load_frags(bf[1], 1, cn, gID, tig);
    load_frags(bf[2], 2, cn, gID, tig);

    __syncthreads();   // x2s visible

    // free-running main loop, unrolled x4 over the register ring
    for (int s = 0; s < NSLICES; s += 4) {
        const int kb = s >> 6;
        const int c  = s & 63;

#pragma unroll
        for (int u = 0; u < 4; u++) {
            int sp = s + u + PF;
            load_frags(bf[(s + u + PF) & 3], (sp < NSLICES) ? sp : NSLICES - 1,
                       cn, gID, tig);
            if (kb == 0)
                chunk_mma<true >(bf[(s + u) & 3], x2s, bvec, A, y, c + u, rm, cn, gID, tig);
            else
                chunk_mma<false>(bf[(s + u) & 3], x2s, bvec, A, y, c + u, rm, cn, gID, tig);
        }

        if (c == 60 && kb + 1 < KB_STEPS)
            load_A(A, x1, tok0, kb + 1, rm, gID, tig);
    }

    // write y
#pragma unroll
    for (int mt = 0; mt < 2; mt++)
#pragma unroll
        for (int h = 0; h < 2; h++) {
            int row = tok0 + rm + mt * 16 + gID + h * 8;
#pragma unroll
            for (int nt = 0; nt < 2; nt++) {
                float2 v;
                v.x = y[mt][nt][h * 2 + 0];
                v.y = y[mt][nt][h * 2 + 1];
                *reinterpret_cast<float2*>(
                    out + (size_t)row * 64 + cn + nt * 8 + tig * 2) = v;
            }
        }
}

extern "C" void kernel_launch(void* const* d_in, const int* in_sizes, int n_in,
                              void* d_out, int out_size) {
    const float* x1   = (const float*)d_in[0];
    const float* x2   = (const float*)d_in[1];
    const float* W    = (const float*)d_in[2];
    const float* bvec = (const float*)d_in[3];
    float* out = (float*)d_out;
    (void)in_sizes; (void)n_in; (void)out_size;

    prep_kernel<<<2048, 256>>>(W);
    metaLinear_kernel<<<NUM_TILES, THREADS, SMEM_BYTES>>>(x1, x2, bvec, out);
}

// round 11
// speedup vs baseline: 1.4114x; 1.4114x over previous
#include <cuda_runtime.h>
#include <cuda_fp16.h>
#include <cstdint>

// ---------------- configuration ----------------
#define TOK_TILE     64
#define NUM_TILES    256          // 16384 / 64  -> 2 CTAs resident per SM
#define THREADS      256          // 8 warps: 2 m-groups x 4 n-groups (Mw=32, Nw=16)
#define KB_STEPS     8            // K=256 in blocks of 32
#define NCHUNKS      64
#define NSLICES      (KB_STEPS * NCHUNKS)   // 512
#define SLICE_WORDS  1024         // 64 o x 32 k halves = 1024 b32 words

// smem: only the x2 tile
#define X2_STRIDE    68
#define SMEM_BYTES   (TOK_TILE * X2_STRIDE * 4)   // 17408

// W pre-converted to fp16, fragment-ordered per (kb, c) slice
__device__ uint32_t g_Wh[4096 * 128];   // 2 MB

static __device__ __forceinline__ uint32_t pack_h2(float lo, float hi) {
    uint32_t r;
    asm("cvt.rn.f16x2.f32 %0, %1, %2;" : "=r"(r) : "f"(hi), "f"(lo));
    return r;
}
// f16-accumulator HMMA: D(2xf16x2) = A*B + C
static __device__ __forceinline__ void mma_h_init(uint32_t& d0, uint32_t& d1,
                                                  const uint32_t* a, uint32_t b0, uint32_t b1,
                                                  uint32_t c0, uint32_t c1) {
    asm("mma.sync.aligned.m16n8k16.row.col.f16.f16.f16.f16 "
        "{%0,%1}, {%2,%3,%4,%5}, {%6,%7}, {%8,%9};"
        : "=r"(d0), "=r"(d1)
        : "r"(a[0]), "r"(a[1]), "r"(a[2]), "r"(a[3]), "r"(b0), "r"(b1),
          "r"(c0), "r"(c1));
}
static __device__ __forceinline__ void mma_h_acc(uint32_t& d0, uint32_t& d1,
                                                 const uint32_t* a, uint32_t b0, uint32_t b1) {
    asm("mma.sync.aligned.m16n8k16.row.col.f16.f16.f16.f16 "
        "{%0,%1}, {%2,%3,%4,%5}, {%6,%7}, {%0,%1};"
        : "+r"(d0), "+r"(d1)
        : "r"(a[0]), "r"(a[1]), "r"(a[2]), "r"(a[3]), "r"(b0), "r"(b1));
}
static __device__ __forceinline__ float2 h2f2(uint32_t p) {
    __half2 h = *reinterpret_cast<__half2*>(&p);
    return __half22float2(h);
}

// -------- W pre-transform: fp32 -> f16x2, fragment order (unchanged from R9) --------
__global__ void prep_kernel(const float* __restrict__ W) {
    int idx = blockIdx.x * 256 + threadIdx.x;      // 524,288 threads
    int s   = idx >> 10;
    int rem = idx & 1023;
    int o   = rem >> 4;
    int r   = (rem >> 2) & 3;
    int q   = rem & 3;
    int ks  = q >> 1, hb = q & 1;
    int kb  = s >> 6, c = s & 63;
    const float* src = W + (size_t)(c * 64 + o) * 256 + kb * 32 + ks * 16 + hb * 8 + r * 2;
    g_Wh[idx] = pack_h2(src[0], src[1]);
}

// this warp's B fragments for slice s: 1 LDG.128 per nt, fully coalesced
static __device__ __forceinline__ void load_frags(uint32_t bf[2][4], int s,
                                                  int cn, int gID, int tig) {
    const uint4* base = reinterpret_cast<const uint4*>(g_Wh) + (size_t)s * (SLICE_WORDS / 4);
#pragma unroll
    for (int nt = 0; nt < 2; nt++) {
        int o = cn + nt * 8 + gID;
        uint4 v = __ldg(base + o * 4 + tig);
        bf[nt][0] = v.x; bf[nt][1] = v.y; bf[nt][2] = v.z; bf[nt][3] = v.w;
    }
}

// A fragments (x1 -> fp16) for one k-block; reused across all 64 chunks
static __device__ __forceinline__ void load_A(uint32_t A[2][2][4],
                                              const float* __restrict__ x1,
                                              int tok0, int kb, int rm, int gID, int tig) {
    const float* base = x1 + (size_t)tok0 * 256 + kb * 32;
#pragma unroll
    for (int mt = 0; mt < 2; mt++) {
        const float* r0 = base + (size_t)(rm + mt * 16 + gID) * 256;
        const float* r1 = r0 + 8 * 256;
#pragma unroll
        for (int ks = 0; ks < 2; ks++) {
            int k0 = ks * 16 + tig * 2;
            float2 a0 = *reinterpret_cast<const float2*>(r0 + k0);
            float2 a1 = *reinterpret_cast<const float2*>(r1 + k0);
            float2 a2 = *reinterpret_cast<const float2*>(r0 + k0 + 8);
            float2 a3 = *reinterpret_cast<const float2*>(r1 + k0 + 8);
            A[mt][ks][0] = pack_h2(a0.x, a0.y);
            A[mt][ks][1] = pack_h2(a1.x, a1.y);
            A[mt][ks][2] = pack_h2(a2.x, a2.y);
            A[mt][ks][3] = pack_h2(a3.x, a3.y);
        }
    }
}

// one chunk: 8 HMMA (f16 accum over K=32) + fp32 epilogue
template <bool FIRST>
static __device__ __forceinline__ void chunk_mma(
    const uint32_t bf[2][4], const float* __restrict__ x2s,
    const float* __restrict__ bvec, const uint32_t A[2][2][4],
    float y[2][2][4], int c, int rm, int cn, int gID, int tig)
{
    float xv[2][2];
#pragma unroll
    for (int mt = 0; mt < 2; mt++) {
        xv[mt][0] = x2s[(rm + mt * 16 + gID) * X2_STRIDE + c];
        xv[mt][1] = x2s[(rm + mt * 16 + gID + 8) * X2_STRIDE + c];
    }
#pragma unroll
    for (int nt = 0; nt < 2; nt++) {
        uint32_t cb = 0;   // f16x2 zero
        if (FIRST) {
            float2 bb = __ldg(reinterpret_cast<const float2*>(
                bvec + c * 64 + cn + nt * 8 + tig * 2));
            cb = pack_h2(bb.x, bb.y);
        }
#pragma unroll
        for (int mt = 0; mt < 2; mt++) {
            uint32_t d0, d1;
            mma_h_init(d0, d1, A[mt][0], bf[nt][0], bf[nt][1], cb, cb);
            mma_h_acc (d0, d1, A[mt][1], bf[nt][2], bf[nt][3]);
            float2 lo = h2f2(d0);   // row gID,   cols (tig*2, tig*2+1)
            float2 hi = h2f2(d1);   // row gID+8, same cols
            y[mt][nt][0] = fmaf(xv[mt][0], lo.x, y[mt][nt][0]);
            y[mt][nt][1] = fmaf(xv[mt][0], lo.y, y[mt][nt][1]);
            y[mt][nt][2] = fmaf(xv[mt][1], hi.x, y[mt][nt][2]);
            y[mt][nt][3] = fmaf(xv[mt][1], hi.y, y[mt][nt][3]);
        }
    }
}

__global__ void __launch_bounds__(THREADS, 2)
metaLinear_kernel(const float* __restrict__ x1, const float* __restrict__ x2,
                  const float* __restrict__ bvec, float* __restrict__ out)
{
    extern __shared__ float x2s[];

    const int tid  = threadIdx.x;
    const int lane = tid & 31, wid = tid >> 5;
    const int wm = wid >> 2, wn = wid & 3;          // 2 m-groups x 4 n-groups
    const int gID = lane >> 2, tig = lane & 3;
    const int tok0 = blockIdx.x * TOK_TILE;
    const int rm = wm * 32;
    const int cn = wn * 16;

    // stage x2 tile (padded stride); the ONLY block barrier
    for (int i = tid; i < TOK_TILE * 64; i += THREADS) {
        int r = i >> 6, c = i & 63;
        x2s[r * X2_STRIDE + c] = x2[(size_t)(tok0 + r) * 64 + c];
    }

    uint32_t A[2][2][4];
    float y[2][2][4];
#pragma unroll
    for (int mt = 0; mt < 2; mt++)
#pragma unroll
        for (int nt = 0; nt < 2; nt++)
#pragma unroll
            for (int j = 0; j < 4; j++) y[mt][nt][j] = 0.0f;

    load_A(A, x1, tok0, 0, rm, gID, tig);

    uint32_t bf0[2][4], bf1[2][4];
    load_frags(bf0, 0, cn, gID, tig);

    __syncthreads();   // x2s visible

    // free-running main loop, register double-buffered B fragments (R9 structure)
    for (int s = 0; s < NSLICES; s += 2) {
        const int kb = s >> 6;
        const int c  = s & 63;

        load_frags(bf1, s + 1, cn, gID, tig);
        if (kb == 0)
            chunk_mma<true >(bf0, x2s, bvec, A, y, c, rm, cn, gID, tig);
        else
            chunk_mma<false>(bf0, x2s, bvec, A, y, c, rm, cn, gID, tig);

        int s2 = (s + 2 < NSLICES) ? s + 2 : NSLICES - 1;
        load_frags(bf0, s2, cn, gID, tig);
        if (kb == 0)
            chunk_mma<true >(bf1, x2s, bvec, A, y, c + 1, rm, cn, gID, tig);
        else
            chunk_mma<false>(bf1, x2s, bvec, A, y, c + 1, rm, cn, gID, tig);

        if (c == 62 && kb + 1 < KB_STEPS)
            load_A(A, x1, tok0, kb + 1, rm, gID, tig);
    }

    // write y
#pragma unroll
    for (int mt = 0; mt < 2; mt++)
#pragma unroll
        for (int h = 0; h < 2; h++) {
            int row = tok0 + rm + mt * 16 + gID + h * 8;
#pragma unroll
            for (int nt = 0; nt < 2; nt++) {
                float2 v;
                v.x = y[mt][nt][h * 2 + 0];
                v.y = y[mt][nt][h * 2 + 1];
                *reinterpret_cast<float2*>(
                    out + (size_t)row * 64 + cn + nt * 8 + tig * 2) = v;
            }
        }
}

extern "C" void kernel_launch(void* const* d_in, const int* in_sizes, int n_in,
                              void* d_out, int out_size) {
    const float* x1   = (const float*)d_in[0];
    const float* x2   = (const float*)d_in[1];
    const float* W    = (const float*)d_in[2];
    const float* bvec = (const float*)d_in[3];
    float* out = (float*)d_out;
    (void)in_sizes; (void)n_in; (void)out_size;

    prep_kernel<<<2048, 256>>>(W);
    metaLinear_kernel<<<NUM_TILES, THREADS, SMEM_BYTES>>>(x1, x2, bvec, out);
}